// round 2
// baseline (speedup 1.0000x reference)
#include <cuda_runtime.h>
#include <cstddef>

#define NN 50000
#define EE 800000

// ---------------- scratch ----------------
__device__ float g_xw [(size_t)NN * 128];   // x @ W1^T           [N,128]
__device__ float g_t  [(size_t)NN * 64];    // relu(adj@xw) @ W2^T [N,64]
__device__ float g_W1T[128 * 128];          // k-major: W1T[k*128+c] = W1[c*128+k]
__device__ float g_W2T[128 * 64];           // k-major: W2T[k*64+c]  = W2[c*128+k]
__device__ int   g_cnt[NN];
__device__ int   g_rowstart[NN + 1];
__device__ int   g_epos[NN];
__device__ int2  g_edge[EE];                // packed (src, val bits)

// ---------------- f32x2 helpers (Blackwell packed fp32) ----------------
__device__ __forceinline__ unsigned long long pack2(float x, float y) {
    unsigned long long r;
    asm("mov.b64 %0, {%1, %2};" : "=l"(r) : "f"(x), "f"(y));
    return r;
}
__device__ __forceinline__ unsigned long long ffma2(unsigned long long a,
                                                    unsigned long long b,
                                                    unsigned long long c) {
    unsigned long long d;
    asm("fma.rn.f32x2 %0, %1, %2, %3;" : "=l"(d) : "l"(a), "l"(b), "l"(c));
    return d;
}
__device__ __forceinline__ float2 unpack2(unsigned long long v) {
    float2 f;
    asm("mov.b64 {%0, %1}, %2;" : "=f"(f.x), "=f"(f.y) : "l"(v));
    return f;
}

// ---------------- prep: zero counters + transpose weights ----------------
__global__ void prep_k(const float* __restrict__ W1, const float* __restrict__ W2) {
    int i = blockIdx.x * blockDim.x + threadIdx.x;
    if (i < NN) g_cnt[i] = 0;
    if (i < 128 * 128) {
        int c = i >> 7, k = i & 127;
        g_W1T[k * 128 + c] = W1[i];
    }
    if (i < 64 * 128) {
        int c = i >> 7, k = i & 127;
        g_W2T[k * 64 + c] = W2[i];
    }
}

__global__ void hist_k(const int* __restrict__ dst) {
    int e = blockIdx.x * blockDim.x + threadIdx.x;
    if (e < EE) atomicAdd(&g_cnt[dst[e]], 1);
}

// single-block exclusive scan over g_cnt -> g_rowstart / g_epos
__global__ void scan_k() {
    __shared__ int warp_excl[32];
    __shared__ int s_carry;
    const int tid  = threadIdx.x;
    const int lane = tid & 31;
    const int wid  = tid >> 5;
    if (tid == 0) s_carry = 0;
    __syncthreads();

    for (int base = 0; base < NN; base += 1024) {
        int i = base + tid;
        int v = (i < NN) ? g_cnt[i] : 0;
        int incl = v;
        #pragma unroll
        for (int off = 1; off < 32; off <<= 1) {
            int t = __shfl_up_sync(0xffffffffu, incl, off);
            if (lane >= off) incl += t;
        }
        if (lane == 31) warp_excl[wid] = incl;
        __syncthreads();
        if (wid == 0) {
            int ws = warp_excl[lane];
            int wincl = ws;
            #pragma unroll
            for (int off = 1; off < 32; off <<= 1) {
                int t = __shfl_up_sync(0xffffffffu, wincl, off);
                if (lane >= off) wincl += t;
            }
            warp_excl[lane] = wincl - ws;
        }
        __syncthreads();
        int excl = (incl - v) + warp_excl[wid] + s_carry;
        if (i < NN) { g_rowstart[i] = excl; g_epos[i] = excl; }
        __syncthreads();
        if (tid == 1023) s_carry = excl + v;
        __syncthreads();
    }
    if (threadIdx.x == 0) g_rowstart[NN] = s_carry;
}

__global__ void scatter_k(const int* __restrict__ src,
                          const int* __restrict__ dst,
                          const float* __restrict__ vals) {
    int e = blockIdx.x * blockDim.x + threadIdx.x;
    if (e < EE) {
        int d = dst[e];
        int p = atomicAdd(&g_epos[d], 1);
        g_edge[p] = make_int2(src[e], __float_as_int(vals[e]));
    }
}

// ---------------- gemm1: xw = x @ W1^T  [N,128], f32x2 core ----------------
__global__ void __launch_bounds__(256) gemm1_k(const float* __restrict__ x) {
    extern __shared__ float sm[];
    float* As = sm;               // [128][132]
    float* Bs = sm + 128 * 132;   // [128][128] k-major
    const int tid = threadIdx.x;
    const int r0  = blockIdx.x * 128;

    #pragma unroll
    for (int i = 0; i < 16; i++) {
        int idx = tid + i * 256;
        int r = idx >> 5, kq = idx & 31;
        float4 v = make_float4(0.f, 0.f, 0.f, 0.f);
        if (r0 + r < NN) v = *(const float4*)(x + (size_t)(r0 + r) * 128 + kq * 4);
        *(float4*)(As + r * 132 + kq * 4) = v;
    }
    #pragma unroll
    for (int i = 0; i < 16; i++) {
        int idx = tid + i * 256;
        ((float4*)Bs)[idx] = ((const float4*)g_W1T)[idx];
    }
    __syncthreads();

    const int tr = tid >> 4;   // 0..15
    const int tc = tid & 15;   // 0..15  (pair-column group)
    unsigned long long acc[8][4];
    #pragma unroll
    for (int i = 0; i < 8; i++)
        #pragma unroll
        for (int j = 0; j < 4; j++) acc[i][j] = 0ull;

    const float* Abase = As + tr * 8 * 132;
    const float* Bbase = Bs + 2 * tc;

    #pragma unroll 8
    for (int k = 0; k < 128; k++) {
        unsigned long long aa[8], b[4];
        #pragma unroll
        for (int i = 0; i < 8; i++) {
            float a = Abase[i * 132 + k];
            aa[i] = pack2(a, a);
        }
        #pragma unroll
        for (int j = 0; j < 4; j++)
            b[j] = *(const unsigned long long*)(Bbase + k * 128 + 32 * j);
        #pragma unroll
        for (int i = 0; i < 8; i++)
            #pragma unroll
            for (int j = 0; j < 4; j++) acc[i][j] = ffma2(aa[i], b[j], acc[i][j]);
    }

    #pragma unroll
    for (int i = 0; i < 8; i++) {
        int r = r0 + tr * 8 + i;
        if (r < NN) {
            #pragma unroll
            for (int j = 0; j < 4; j++) {
                float2 v = unpack2(acc[i][j]);
                *(float2*)(g_xw + (size_t)r * 128 + 2 * tc + 32 * j) = v;
            }
        }
    }
}

// ---------------- fused: h_tile = relu(adj @ xw) (in smem) ; t = h_tile @ W2^T ----------------
__global__ void __launch_bounds__(256) fused1_k() {
    extern __shared__ float sm[];
    float* As = sm;              // [128][132]  relu(spmm) tile
    float* Bs = sm + 128 * 132;  // [128][64]   W2T k-major
    const int tid  = threadIdx.x;
    const int lane = tid & 31;
    const int w    = tid >> 5;   // warp 0..7
    const int r0   = blockIdx.x * 128;

    // load W2T
    #pragma unroll
    for (int i = 0; i < 8; i++) {
        int idx = tid + i * 256;
        ((float4*)Bs)[idx] = ((const float4*)g_W2T)[idx];
    }

    // spmm + relu into As: warp w handles 16 rows
    const float4* xb = (const float4*)g_xw;
    for (int i = 0; i < 16; i++) {
        int rl = w * 16 + i;          // local row
        int r  = r0 + rl;
        float4 acc = make_float4(0.f, 0.f, 0.f, 0.f);
        if (r < NN) {
            int beg = g_rowstart[r];
            int end = g_rowstart[r + 1];
            #pragma unroll 2
            for (int j = beg; j < end; j++) {
                int2  e = __ldg(&g_edge[j]);
                float v = __int_as_float(e.y);
                float4 xv = __ldg(&xb[(size_t)e.x * 32 + lane]);
                acc.x = fmaf(v, xv.x, acc.x);
                acc.y = fmaf(v, xv.y, acc.y);
                acc.z = fmaf(v, xv.z, acc.z);
                acc.w = fmaf(v, xv.w, acc.w);
            }
        }
        acc.x = fmaxf(acc.x, 0.f); acc.y = fmaxf(acc.y, 0.f);
        acc.z = fmaxf(acc.z, 0.f); acc.w = fmaxf(acc.w, 0.f);
        *(float4*)(As + rl * 132 + lane * 4) = acc;
    }
    __syncthreads();

    // gemm 128x64 from As x Bs -> g_t
    const int tr = tid >> 4;
    const int tc = tid & 15;
    unsigned long long acc[8][2];
    #pragma unroll
    for (int i = 0; i < 8; i++) { acc[i][0] = 0ull; acc[i][1] = 0ull; }

    const float* Abase = As + tr * 8 * 132;
    const float* Bbase = Bs + 2 * tc;

    #pragma unroll 8
    for (int k = 0; k < 128; k++) {
        unsigned long long aa[8], b[2];
        #pragma unroll
        for (int i = 0; i < 8; i++) {
            float a = Abase[i * 132 + k];
            aa[i] = pack2(a, a);
        }
        b[0] = *(const unsigned long long*)(Bbase + k * 64);
        b[1] = *(const unsigned long long*)(Bbase + k * 64 + 32);
        #pragma unroll
        for (int i = 0; i < 8; i++) {
            acc[i][0] = ffma2(aa[i], b[0], acc[i][0]);
            acc[i][1] = ffma2(aa[i], b[1], acc[i][1]);
        }
    }

    #pragma unroll
    for (int i = 0; i < 8; i++) {
        int r = r0 + tr * 8 + i;
        if (r < NN) {
            float2 v0 = unpack2(acc[i][0]);
            float2 v1 = unpack2(acc[i][1]);
            *(float2*)(g_t + (size_t)r * 64 + 2 * tc)      = v0;
            *(float2*)(g_t + (size_t)r * 64 + 2 * tc + 32) = v1;
        }
    }
}

// ---------------- fused: out = softmax(adj @ t), one warp per node ----------------
__global__ void fused2_k(float* __restrict__ out) {
    int gtid = blockIdx.x * blockDim.x + threadIdx.x;
    int w    = gtid >> 5;
    int lane = gtid & 31;
    if (w >= NN) return;
    int beg = g_rowstart[w];
    int end = g_rowstart[w + 1];
    float2 acc = make_float2(0.f, 0.f);
    const float2* tb = (const float2*)g_t;
    #pragma unroll 2
    for (int j = beg; j < end; j++) {
        int2  e = __ldg(&g_edge[j]);
        float v = __int_as_float(e.y);
        float2 xv = __ldg(&tb[(size_t)e.x * 32 + lane]);
        acc.x = fmaf(v, xv.x, acc.x);
        acc.y = fmaf(v, xv.y, acc.y);
    }
    float m = fmaxf(acc.x, acc.y);
    #pragma unroll
    for (int o = 16; o; o >>= 1) m = fmaxf(m, __shfl_xor_sync(0xffffffffu, m, o));
    float e0 = __expf(acc.x - m);
    float e1 = __expf(acc.y - m);
    float s = e0 + e1;
    #pragma unroll
    for (int o = 16; o; o >>= 1) s += __shfl_xor_sync(0xffffffffu, s, o);
    float inv = 1.0f / s;
    ((float2*)out)[(size_t)w * 32 + lane] = make_float2(e0 * inv, e1 * inv);
}

// ---------------- launch ----------------
extern "C" void kernel_launch(void* const* d_in, const int* in_sizes, int n_in,
                              void* d_out, int out_size) {
    const float* x    = (const float*)d_in[0];
    const float* vals = (const float*)d_in[1];
    const float* W1   = (const float*)d_in[2];
    const float* W2   = (const float*)d_in[3];
    const int*   src  = (const int*)d_in[4];
    const int*   dst  = (const int*)d_in[5];
    float*       out  = (float*)d_out;

    const int SMEM_G1 = (128 * 132 + 128 * 128) * 4;  // 133120 B
    const int SMEM_F1 = (128 * 132 + 128 * 64) * 4;   // 100352 B
    cudaFuncSetAttribute(gemm1_k,  cudaFuncAttributeMaxDynamicSharedMemorySize, SMEM_G1);
    cudaFuncSetAttribute(fused1_k, cudaFuncAttributeMaxDynamicSharedMemorySize, SMEM_F1);

    const int TB = 256;
    prep_k    <<<(NN + TB - 1) / TB, TB>>>(W1, W2);
    hist_k    <<<(EE + TB - 1) / TB, TB>>>(dst);
    scan_k    <<<1, 1024>>>();
    scatter_k <<<(EE + TB - 1) / TB, TB>>>(src, dst, vals);

    gemm1_k   <<<(NN + 127) / 128, TB, SMEM_G1>>>(x);
    fused1_k  <<<(NN + 127) / 128, TB, SMEM_F1>>>();
    fused2_k  <<<(NN * 32 + TB - 1) / TB, TB>>>(out);
}